// round 15
// baseline (speedup 1.0000x reference)
#include <cuda_runtime.h>
#include <cstdint>

// nu_grid_sampler: out[b,c,n] = x[b,c,px,py], x:(8,128,256,256) f32,
// coords:(8,32768,2) f32, out:(8,128,32768) f32.
//
// R15 = R14 (line-sorted direct gather, the 90.6us winner: counting-sort
// points by 128B line -> near-coalesced LDG gather, STS scatter into a 128KB
// smem out-plane) with the tail cp.async.bulk store + wait replaced by a
// dense float4 STG.128 copy loop. STGs retire asynchronously after block
// exit, removing ~1.5us/block x 7 waves of tail serialization that the TMA
// wait_group imposed. zero_kernel replaced by cudaMemsetAsync.

#define GS_B 8
#define GS_C 128
#define GS_NX 256
#define GS_NY 256
#define GS_N 32768
#define GS_PIX (GS_NX * GS_NY)     // 65536
#define NBUCK 2048                  // idx>>5 : one 128B line per bucket
#define K2_THREADS 1024
#define ITERS (GS_N / K2_THREADS)   // 32
#define OBUF_BYTES (GS_N * 4)       // 128KB

__device__ unsigned g_idx[GS_B * GS_N];      // raw pixel idx per point
__device__ unsigned g_sorted[GS_B * GS_N];   // idx | (j<<16), line-sorted
__device__ int g_hist[GS_B * NBUCK];
__device__ int g_cursor[GS_B * NBUCK];

__device__ __forceinline__ unsigned compute_idx(float cy, float cx) {
    float pxf = fminf(fmaxf(cx * (float)(GS_NX - 1), 0.0f), (float)GS_NX);
    float pyf = fminf(fmaxf(cy * (float)(GS_NY - 1), 0.0f), (float)GS_NY);
    int idx = (int)pxf * GS_NY + (int)pyf;
    return (unsigned)min(idx, GS_PIX - 1);   // take_along_axis clamp
}

__global__ __launch_bounds__(1024)
void hist_kernel(const float* __restrict__ coords) {
    __shared__ int lh[NBUCK];
    const int t = threadIdx.x;
    const int b = blockIdx.y;
    const int j = blockIdx.x * 1024 + t;
    lh[t] = 0; lh[t + 1024] = 0;
    __syncthreads();
    float2 co = reinterpret_cast<const float2*>(coords)[(size_t)b * GS_N + j];
    unsigned idx = compute_idx(co.x, co.y);
    g_idx[b * GS_N + j] = idx;
    atomicAdd(&lh[idx >> 5], 1);
    __syncthreads();
    if (lh[t])        atomicAdd(&g_hist[b * NBUCK + t],        lh[t]);
    if (lh[t + 1024]) atomicAdd(&g_hist[b * NBUCK + t + 1024], lh[t + 1024]);
}

__global__ __launch_bounds__(1024)
void prefix_kernel() {            // one block per batch: exclusive scan of 2048
    __shared__ int sc[NBUCK];
    __shared__ int ps[1024];
    const int t = threadIdx.x;
    const int b = blockIdx.x;
    sc[t]        = g_hist[b * NBUCK + t];
    sc[t + 1024] = g_hist[b * NBUCK + t + 1024];
    __syncthreads();
    int pairsum = sc[2 * t] + sc[2 * t + 1];
    ps[t] = pairsum;
    __syncthreads();
    for (int off = 1; off < 1024; off <<= 1) {      // Hillis-Steele inclusive
        int v = (t >= off) ? ps[t - off] : 0;
        __syncthreads();
        ps[t] += v;
        __syncthreads();
    }
    int base = ps[t] - pairsum;                      // exclusive over pairs
    g_cursor[b * NBUCK + 2 * t]     = base;
    g_cursor[b * NBUCK + 2 * t + 1] = base + sc[2 * t];
}

__global__ __launch_bounds__(1024)
void scatter_kernel() {
    __shared__ int lh[NBUCK];
    __shared__ int lbase[NBUCK];
    const int t = threadIdx.x;
    const int b = blockIdx.y;
    const int j = blockIdx.x * 1024 + t;
    lh[t] = 0; lh[t + 1024] = 0;
    __syncthreads();
    unsigned idx = g_idx[b * GS_N + j];
    int s = idx >> 5;
    int r = atomicAdd(&lh[s], 1);
    __syncthreads();
    if (lh[t])        lbase[t]        = atomicAdd(&g_cursor[b * NBUCK + t],        lh[t]);
    if (lh[t + 1024]) lbase[t + 1024] = atomicAdd(&g_cursor[b * NBUCK + t + 1024], lh[t + 1024]);
    __syncthreads();
    g_sorted[b * GS_N + lbase[s] + r] = idx | ((unsigned)j << 16);
}

__global__ __launch_bounds__(K2_THREADS, 1)
void gather_kernel(const float* __restrict__ x, float* __restrict__ out) {
    extern __shared__ float obuf[];              // 32768 floats = 128KB
    const int tid = threadIdx.x;
    const int bc  = blockIdx.x;                  // b*128 + c
    const int b   = bc >> 7;

    const float* __restrict__ plane    = x + ((size_t)bc << 16);
    const unsigned* __restrict__ ents  = g_sorted + b * GS_N;

    // 32 iterations: coalesced entry load, near-coalesced sorted gather,
    // STS scatter into the smem out-plane.
    #pragma unroll 8
    for (int it = 0; it < ITERS; ++it) {
        unsigned e = __ldg(ents + (it << 10) + tid);
        obuf[e >> 16] = __ldg(plane + (e & 0xFFFFu));
    }
    __syncthreads();

    // Dense float4 flush: STG.128 retires asynchronously (no tail wait).
    float* __restrict__ ob = out + ((size_t)bc << 15);
    #pragma unroll
    for (int q = 0; q < GS_N / (K2_THREADS * 4); ++q) {   // 8 iters
        int o = (q * K2_THREADS + tid) * 4;
        float4 v = *reinterpret_cast<const float4*>(&obuf[o]);
        *reinterpret_cast<float4*>(&ob[o]) = v;
    }
}

extern "C" void kernel_launch(void* const* d_in, const int* in_sizes, int n_in,
                              void* d_out, int out_size) {
    const float* x      = (const float*)d_in[0];   // (8,128,256,256) f32
    const float* coords = (const float*)d_in[1];   // (8,32768,2) f32
    float* out          = (float*)d_out;           // (8,128,32768) f32

    static void* hist_addr = nullptr;
    static int smem_set = 0;
    if (!smem_set) {
        cudaFuncSetAttribute(gather_kernel,
                             cudaFuncAttributeMaxDynamicSharedMemorySize,
                             OBUF_BYTES);
        cudaGetSymbolAddress(&hist_addr, g_hist);
        smem_set = 1;
    }

    cudaMemsetAsync(hist_addr, 0, GS_B * NBUCK * sizeof(int));
    hist_kernel<<<dim3(GS_N / 1024, GS_B), 1024>>>(coords);
    prefix_kernel<<<GS_B, 1024>>>();
    scatter_kernel<<<dim3(GS_N / 1024, GS_B), 1024>>>();
    gather_kernel<<<GS_B * GS_C, K2_THREADS, OBUF_BYTES>>>(x, out);
}